// round 13
// baseline (speedup 1.0000x reference)
#include <cuda_runtime.h>
#include <cuda_bf16.h>
#include <math.h>
#include <cstdint>

// Problem constants
#define B_  4
#define S_  2048
#define D_  1024
#define H_  16
#define HD_ 64
#define M_  (B_ * S_)        // 8192 rows

// Scratch buffers
__device__ __nv_bfloat16 g_qkvh[(size_t)M_ * 3 * D_];   // [8192][3072]
__device__ __nv_bfloat16 g_qkvl[(size_t)M_ * 3 * D_];
__device__ __nv_bfloat16 g_x_hi[(size_t)M_ * D_];
__device__ __nv_bfloat16 g_x_lo[(size_t)M_ * D_];
__device__ __nv_bfloat16 g_attn_hi[(size_t)M_ * D_];
__device__ __nv_bfloat16 g_attn_lo[(size_t)M_ * D_];
__device__ __nv_bfloat16 g_wqkvT_hi[(size_t)3 * D_ * D_];   // [3072][1024]
__device__ __nv_bfloat16 g_wqkvT_lo[(size_t)3 * D_ * D_];
__device__ __nv_bfloat16 g_woutT_hi[(size_t)D_ * D_];       // [1024][1024]
__device__ __nv_bfloat16 g_woutT_lo[(size_t)D_ * D_];

// ---------------------------------------------------------------------------
// PTX helpers (baseline PTX only: ldmatrix, mma.sync, cp.async)
// ---------------------------------------------------------------------------
__device__ __forceinline__ uint32_t smem_u32(const void* p) {
    uint32_t a;
    asm("{ .reg .u64 t; cvta.to.shared.u64 t, %1; cvt.u32.u64 %0, t; }" : "=r"(a) : "l"(p));
    return a;
}
__device__ __forceinline__ void cpa16(uint32_t s, const void* g) {
    asm volatile("cp.async.cg.shared.global [%0], [%1], 16;" :: "r"(s), "l"(g));
}
#define CPA_COMMIT() asm volatile("cp.async.commit_group;" ::: "memory")
#define CPA_WAIT(n)  asm volatile("cp.async.wait_group %0;" :: "n"(n) : "memory")

#define LDSM_X4(r0, r1, r2, r3, addr) \
    asm volatile("ldmatrix.sync.aligned.m8n8.x4.shared.b16 {%0,%1,%2,%3}, [%4];" \
                 : "=r"(r0), "=r"(r1), "=r"(r2), "=r"(r3) : "r"(addr))
#define LDSM_X4T(r0, r1, r2, r3, addr) \
    asm volatile("ldmatrix.sync.aligned.m8n8.x4.trans.shared.b16 {%0,%1,%2,%3}, [%4];" \
                 : "=r"(r0), "=r"(r1), "=r"(r2), "=r"(r3) : "r"(addr))

#define MMA16816(d, a, bb0, bb1) \
    asm volatile("mma.sync.aligned.m16n8k16.row.col.f32.bf16.bf16.f32 " \
                 "{%0,%1,%2,%3}, {%4,%5,%6,%7}, {%8,%9}, {%0,%1,%2,%3};" \
                 : "+f"((d)[0]), "+f"((d)[1]), "+f"((d)[2]), "+f"((d)[3]) \
                 : "r"((a)[0]), "r"((a)[1]), "r"((a)[2]), "r"((a)[3]), \
                   "r"(bb0), "r"(bb1))

__device__ __forceinline__ uint32_t pack_hi2(float a, float b) {
    return (uint32_t)__bfloat16_as_ushort(__float2bfloat16(a))
         | ((uint32_t)__bfloat16_as_ushort(__float2bfloat16(b)) << 16);
}
__device__ __forceinline__ uint32_t pack_lo2(float a, float b) {
    __nv_bfloat16 ha = __float2bfloat16(a), hb = __float2bfloat16(b);
    __nv_bfloat16 la = __float2bfloat16(a - __bfloat162float(ha));
    __nv_bfloat16 lb = __float2bfloat16(b - __bfloat162float(hb));
    return (uint32_t)__bfloat16_as_ushort(la) | ((uint32_t)__bfloat16_as_ushort(lb) << 16);
}

// ---------------------------------------------------------------------------
// bf16 split-3 GEMM, pass-merged, 3-stage cp.async pipeline, ONE sync/chunk,
// 64B-pitch rows with XOR swizzle (chunk' = chunk ^ ((row>>1)&3)).
// C = Ahi*Bhi + Ahi*Blo + Alo*Bhi.  A [M][K], B [N][K] (weights transposed).
// Tile 128x128, BK=32, 256 threads (8 warps 2x4, warp tile 64x32), 2 CTA/SM.
// scaleQ: if nonzero and this output tile is in cols [0,1024) (the Q block of
// the qkv projection), scale results by 0.125*log2(e) — folds both the attn
// 1/sqrt(hd) scaling AND the exp->exp2 conversion into the epilogue.
// ---------------------------------------------------------------------------
#define G_AH   0
#define G_AL   8192
#define G_BH   16384
#define G_BL   24576
#define G_STG  32768
#define GEMM_SMEM_BYTES (3 * G_STG)       // 98304

__global__ __launch_bounds__(256, 2)
void gemm_mma_kernel(const __nv_bfloat16* __restrict__ Ahi, const __nv_bfloat16* __restrict__ Alo,
                     const __nv_bfloat16* __restrict__ Bhi, const __nv_bfloat16* __restrict__ Blo,
                     float* __restrict__ Cf, __nv_bfloat16* __restrict__ Ch,
                     __nv_bfloat16* __restrict__ Cl, int Ndim, int Kdim, int scaleQ)
{
    extern __shared__ __align__(16) char smem[];
    const uint32_t sb = smem_u32(smem);

    const int t   = threadIdx.x;
    const int l   = t & 31;
    const int wid = t >> 5;
    const int wm  = wid >> 2;             // 0..1
    const int wn  = wid & 3;              // 0..3
    const int row0 = blockIdx.y * 128, col0 = blockIdx.x * 128;

    const int KCH = Kdim >> 5;            // 32

    const int r1 = t >> 2, cc = t & 3;
    const uint32_t scc = (uint32_t)(cc ^ ((r1 >> 1) & 3));
    const uint32_t so1 = (uint32_t)(r1 * 64) + scc * 16;
    const uint32_t so2 = so1 + 64 * 64;

    float acc[4][4][4];
#pragma unroll
    for (int i = 0; i < 4; i++)
#pragma unroll
        for (int j = 0; j < 4; j++)
#pragma unroll
            for (int k = 0; k < 4; k++) acc[i][j][k] = 0.0f;

    const size_t dA = (size_t)(Alo - Ahi);
    const size_t dB = (size_t)(Blo - Bhi);

    auto issue = [&](int c) {
        const int k0 = c << 5;
        const uint32_t base = sb + (uint32_t)(c % 3) * G_STG;
        const __nv_bfloat16* a1 = Ahi + (size_t)(row0 + r1) * Kdim + k0 + cc * 8;
        const __nv_bfloat16* a2 = a1 + (size_t)64 * Kdim;
        const __nv_bfloat16* b1 = Bhi + (size_t)(col0 + r1) * Kdim + k0 + cc * 8;
        const __nv_bfloat16* b2 = b1 + (size_t)64 * Kdim;
        cpa16(base + G_AH + so1, a1);
        cpa16(base + G_AH + so2, a2);
        cpa16(base + G_AL + so1, a1 + dA);
        cpa16(base + G_AL + so2, a2 + dA);
        cpa16(base + G_BH + so1, b1);
        cpa16(base + G_BH + so2, b2);
        cpa16(base + G_BL + so1, b1 + dB);
        cpa16(base + G_BL + so2, b2 + dB);
        CPA_COMMIT();
    };

    issue(0);
    if (KCH > 1) issue(1);

    const uint32_t a_lrow = (uint32_t)(wm * 64 + (l & 15));
    const uint32_t a_cb   = (uint32_t)(l >> 4);
    const uint32_t sa     = (a_lrow >> 1) & 3;
    const uint32_t b_lrow = (uint32_t)(wn * 32 + ((l >> 4) & 1) * 8 + (l & 7));
    const uint32_t b_cb   = (uint32_t)((l >> 3) & 1);
    const uint32_t sbw    = (b_lrow >> 1) & 3;

    for (int c = 0; c < KCH; c++) {
        if (c + 1 < KCH) CPA_WAIT(1); else CPA_WAIT(0);
        __syncthreads();
        if (c + 2 < KCH) issue(c + 2);

        const uint32_t stg = sb + (uint32_t)(c % 3) * G_STG;
        const uint32_t Ah = stg + G_AH, Al = stg + G_AL;
        const uint32_t Bh = stg + G_BH, Bl = stg + G_BL;
#pragma unroll
        for (int ks = 0; ks < 2; ks++) {
            const uint32_t bsw = ((b_cb + (uint32_t)(ks * 2)) ^ sbw) * 16u;
            uint32_t bfh[2][4], bfl[2][4];
#pragma unroll
            for (int np = 0; np < 2; np++) {
                const uint32_t ro = (b_lrow + (uint32_t)(np * 16)) * 64u + bsw;
                LDSM_X4(bfh[np][0], bfh[np][1], bfh[np][2], bfh[np][3], Bh + ro);
                LDSM_X4(bfl[np][0], bfl[np][1], bfl[np][2], bfl[np][3], Bl + ro);
            }
            const uint32_t asw = ((a_cb + (uint32_t)(ks * 2)) ^ sa) * 16u;
#pragma unroll
            for (int mt = 0; mt < 4; mt++) {
                const uint32_t aro = (a_lrow + (uint32_t)(mt * 16)) * 64u + asw;
                uint32_t af[4];
                LDSM_X4(af[0], af[1], af[2], af[3], Ah + aro);
#pragma unroll
                for (int nt = 0; nt < 4; nt++) {
                    const uint32_t* bp = &bfh[nt >> 1][(nt & 1) * 2];
                    MMA16816(acc[mt][nt], af, bp[0], bp[1]);
                }
#pragma unroll
                for (int nt = 0; nt < 4; nt++) {
                    const uint32_t* bp = &bfl[nt >> 1][(nt & 1) * 2];
                    MMA16816(acc[mt][nt], af, bp[0], bp[1]);
                }
                LDSM_X4(af[0], af[1], af[2], af[3], Al + aro);
#pragma unroll
                for (int nt = 0; nt < 4; nt++) {
                    const uint32_t* bp = &bfh[nt >> 1][(nt & 1) * 2];
                    MMA16816(acc[mt][nt], af, bp[0], bp[1]);
                }
            }
        }
    }

    // Epilogue
    const int erow = row0 + wm * 64 + (l >> 2);
    const int ecol = col0 + wn * 32 + 2 * (l & 3);
    if (Cf) {
#pragma unroll
        for (int mt = 0; mt < 4; mt++)
#pragma unroll
            for (int nt = 0; nt < 4; nt++) {
                float2 v0 = {acc[mt][nt][0], acc[mt][nt][1]};
                float2 v1 = {acc[mt][nt][2], acc[mt][nt][3]};
                *(float2*)(Cf + (size_t)(erow + mt * 16)     * Ndim + ecol + nt * 8) = v0;
                *(float2*)(Cf + (size_t)(erow + mt * 16 + 8) * Ndim + ecol + nt * 8) = v1;
            }
    } else {
        // 0.125 (1/sqrt(64)) * log2(e): S emerges in log2 units -> exp2 softmax
        const float cs = (scaleQ && col0 < 1024) ? 0.18033688011112042f : 1.0f;
#pragma unroll
        for (int mt = 0; mt < 4; mt++)
#pragma unroll
            for (int nt = 0; nt < 4; nt++) {
                float a0 = acc[mt][nt][0] * cs, a1 = acc[mt][nt][1] * cs;
                float a2 = acc[mt][nt][2] * cs, a3 = acc[mt][nt][3] * cs;
                size_t o0 = (size_t)(erow + mt * 16)     * Ndim + ecol + nt * 8;
                size_t o1 = (size_t)(erow + mt * 16 + 8) * Ndim + ecol + nt * 8;
                *(uint32_t*)(Ch + o0) = pack_hi2(a0, a1);
                *(uint32_t*)(Cl + o0) = pack_lo2(a0, a1);
                *(uint32_t*)(Ch + o1) = pack_hi2(a2, a3);
                *(uint32_t*)(Cl + o1) = pack_lo2(a2, a3);
            }
    }
}

// ---------------------------------------------------------------------------
// fp32 -> (hi, lo) bf16 split (for x input)
// ---------------------------------------------------------------------------
__global__ __launch_bounds__(256) void split_kernel(
    const float* __restrict__ in, __nv_bfloat16* __restrict__ hi,
    __nv_bfloat16* __restrict__ lo, int n4)
{
    int i = blockIdx.x * blockDim.x + threadIdx.x;
    if (i >= n4) return;
    float4 v = ((const float4*)in)[i];
    uint2 ph = {pack_hi2(v.x, v.y), pack_hi2(v.z, v.w)};
    uint2 pl = {pack_lo2(v.x, v.y), pack_lo2(v.z, v.w)};
    ((uint2*)hi)[i] = ph;
    ((uint2*)lo)[i] = pl;
}

// ---------------------------------------------------------------------------
// fp32 [R][C] -> transposed bf16 hi/lo [C][R]
// ---------------------------------------------------------------------------
__global__ void tsplit_kernel(const float* __restrict__ in,
                              __nv_bfloat16* __restrict__ hiT,
                              __nv_bfloat16* __restrict__ loT, int R, int Cc)
{
    __shared__ float sm2[32][33];
    int c0 = blockIdx.x * 32, r0 = blockIdx.y * 32;
    int tx = threadIdx.x, ty = threadIdx.y;
#pragma unroll
    for (int i = ty; i < 32; i += 8)
        sm2[i][tx] = in[(size_t)(r0 + i) * Cc + c0 + tx];
    __syncthreads();
#pragma unroll
    for (int i = ty; i < 32; i += 8) {
        float v = sm2[tx][i];
        __nv_bfloat16 h = __float2bfloat16(v);
        __nv_bfloat16 lo = __float2bfloat16(v - __bfloat162float(h));
        size_t o = (size_t)(c0 + i) * R + r0 + tx;
        hiT[o] = h; loT[o] = lo;
    }
}

// ---------------------------------------------------------------------------
// Causal flash attention, pass-merged split-3, 2-stage KV pipeline with ONE
// syncthreads per k-tile, fully-masked warp-tiles skipped, exp2-domain
// softmax (Q pre-scaled by 0.125*log2e in GEMM1), big-first qt ordering.
// 256 thr; warp w: q-rows w*16..+15 of 128.
// ---------------------------------------------------------------------------
#define APB 144
#define AQ_OFF  0
#define AQL_OFF (128 * APB)
#define ASTG0   (2 * 128 * APB)
#define ASTGSZ  (4 * 64 * APB)
#define ATTN_SMEM_BYTES (ASTG0 + 2 * ASTGSZ)   // 110592

__global__ __launch_bounds__(256, 2)
void attn_mma_kernel(const __nv_bfloat16* __restrict__ qkvh,
                     const __nv_bfloat16* __restrict__ qkvl,
                     __nv_bfloat16* __restrict__ outh,
                     __nv_bfloat16* __restrict__ outl)
{
    extern __shared__ __align__(16) char smem[];
    const uint32_t sb = smem_u32(smem);

    const int t = threadIdx.x, l = t & 31, w = t >> 5;
    const int qt = (int)(gridDim.x - 1 - blockIdx.x);   // big-first scheduling
    const int h = blockIdx.y, b = blockIdx.z;
    const int q0 = qt * 128;

    {
#pragma unroll
        for (int i = 0; i < 4; i++) {
            int q = t + i * 256;
            int r = q >> 3, ch = q & 7;
            size_t g = (size_t)(b * S_ + q0 + r) * 3072 + h * HD_ + ch * 8;
            uint32_t s = (uint32_t)(r * APB + ch * 16);
            cpa16(sb + AQ_OFF + s,  qkvh + g);
            cpa16(sb + AQL_OFF + s, qkvl + g);
        }
        CPA_COMMIT();
    }

    const int r_ld = t >> 3, ch_ld = t & 7;
    const uint32_t s_ld = (uint32_t)(r_ld * APB + ch_ld * 16);
    const uint32_t s_ld2 = s_ld + 32 * APB;

    auto issue_kv = [&](int kt) {
        const int k0 = kt * 64;
        const uint32_t base = sb + ASTG0 + (uint32_t)(kt & 1) * ASTGSZ;
        size_t gk1 = (size_t)(b * S_ + k0 + r_ld) * 3072 + 1024 + h * HD_ + ch_ld * 8;
        size_t gk2 = gk1 + (size_t)32 * 3072;
        cpa16(base + s_ld,          qkvh + gk1);
        cpa16(base + s_ld2,         qkvh + gk2);
        cpa16(base + 9216 + s_ld,   qkvl + gk1);
        cpa16(base + 9216 + s_ld2,  qkvl + gk2);
        cpa16(base + 18432 + s_ld,  qkvh + gk1 + 1024);
        cpa16(base + 18432 + s_ld2, qkvh + gk2 + 1024);
        cpa16(base + 27648 + s_ld,  qkvl + gk1 + 1024);
        cpa16(base + 27648 + s_ld2, qkvl + gk2 + 1024);
        CPA_COMMIT();
    };

    issue_kv(0);

    float m0 = -INFINITY, m1 = -INFINITY, lr0 = 0.0f, lr1 = 0.0f;
    float O[8][4];
#pragma unroll
    for (int n = 0; n < 8; n++)
#pragma unroll
        for (int k = 0; k < 4; k++) O[n][k] = 0.0f;

    const uint32_t a_row = (uint32_t)(w * 16 + (l & 15));
    const uint32_t a_kd  = (uint32_t)((l >> 4) * 8);
    const uint32_t bk_j  = (uint32_t)(((l >> 4) & 1) * 8 + (l & 7));
    const uint32_t bk_d  = (uint32_t)(((l >> 3) & 1) * 8);
    const uint32_t bv_j  = (uint32_t)(((l >> 3) & 1) * 8 + (l & 7));
    const uint32_t bv_d  = (uint32_t)((l >> 4) * 8);

    const int ktiles = 2 * qt + 2;
    for (int kt = 0; kt < ktiles; kt++) {
        const int k0 = kt * 64;
        CPA_WAIT(0);
        __syncthreads();                       // publishes stage kt; proves kt-1 compute done
        if (kt + 1 < ktiles) issue_kv(kt + 1); // safe: writes stage (kt-1)&1

        // fully-masked warp-tile? (only possible on the last, second-diagonal tile)
        if (k0 > q0 + w * 16 + 15) continue;

        const uint32_t stg = sb + ASTG0 + (uint32_t)(kt & 1) * ASTGSZ;
        const uint32_t Kh = stg, Kl = stg + 9216;
        const uint32_t Vh = stg + 18432, Vl = stg + 27648;

        float S[8][4];
#pragma unroll
        for (int n = 0; n < 8; n++)
#pragma unroll
            for (int k = 0; k < 4; k++) S[n][k] = 0.0f;

#pragma unroll
        for (int ks = 0; ks < 4; ks++) {
            const uint32_t qro = a_row * APB + (a_kd + (uint32_t)(ks * 16)) * 2u;
            uint32_t aqh[4], aql[4];
            LDSM_X4(aqh[0], aqh[1], aqh[2], aqh[3], sb + AQ_OFF + qro);
            LDSM_X4(aql[0], aql[1], aql[2], aql[3], sb + AQL_OFF + qro);
            const uint32_t kdo = (bk_d + (uint32_t)(ks * 16)) * 2u;
#pragma unroll
            for (int jp = 0; jp < 4; jp++) {
                const uint32_t kro = (bk_j + (uint32_t)(jp * 16)) * APB + kdo;
                uint32_t bkh[4], bkl[4];
                LDSM_X4(bkh[0], bkh[1], bkh[2], bkh[3], Kh + kro);
                LDSM_X4(bkl[0], bkl[1], bkl[2], bkl[3], Kl + kro);
                MMA16816(S[2 * jp],     aqh, bkh[0], bkh[1]);
                MMA16816(S[2 * jp + 1], aqh, bkh[2], bkh[3]);
                MMA16816(S[2 * jp],     aqh, bkl[0], bkl[1]);
                MMA16816(S[2 * jp + 1], aqh, bkl[2], bkl[3]);
                MMA16816(S[2 * jp],     aql, bkh[0], bkh[1]);
                MMA16816(S[2 * jp + 1], aql, bkh[2], bkh[3]);
            }
        }

        // causal mask (S already in log2 domain; no scale pass)
        if (kt >= 2 * qt) {
            const int gi0 = q0 + w * 16 + (l >> 2);
            const int gi1 = gi0 + 8;
#pragma unroll
            for (int n = 0; n < 8; n++) {
                const int gj = k0 + n * 8 + (l & 3) * 2;
                if (gj     > gi0) S[n][0] = -INFINITY;
                if (gj + 1 > gi0) S[n][1] = -INFINITY;
                if (gj     > gi1) S[n][2] = -INFINITY;
                if (gj + 1 > gi1) S[n][3] = -INFINITY;
            }
        }

        float mx0 = -INFINITY, mx1 = -INFINITY;
#pragma unroll
        for (int n = 0; n < 8; n++) {
            mx0 = fmaxf(mx0, fmaxf(S[n][0], S[n][1]));
            mx1 = fmaxf(mx1, fmaxf(S[n][2], S[n][3]));
        }
        mx0 = fmaxf(mx0, __shfl_xor_sync(0xffffffffu, mx0, 1));
        mx0 = fmaxf(mx0, __shfl_xor_sync(0xffffffffu, mx0, 2));
        mx1 = fmaxf(mx1, __shfl_xor_sync(0xffffffffu, mx1, 1));
        mx1 = fmaxf(mx1, __shfl_xor_sync(0xffffffffu, mx1, 2));
        const float mn0 = fmaxf(m0, mx0), mn1 = fmaxf(m1, mx1);
        const float corr0 = exp2f(m0 - mn0), corr1 = exp2f(m1 - mn1);
        m0 = mn0; m1 = mn1;
        float sum0 = 0.0f, sum1 = 0.0f;
#pragma unroll
        for (int n = 0; n < 8; n++) {
            S[n][0] = exp2f(S[n][0] - mn0);
            S[n][1] = exp2f(S[n][1] - mn0);
            S[n][2] = exp2f(S[n][2] - mn1);
            S[n][3] = exp2f(S[n][3] - mn1);
            sum0 += S[n][0] + S[n][1];
            sum1 += S[n][2] + S[n][3];
            O[n][0] *= corr0; O[n][1] *= corr0;
            O[n][2] *= corr1; O[n][3] *= corr1;
        }
        sum0 += __shfl_xor_sync(0xffffffffu, sum0, 1);
        sum0 += __shfl_xor_sync(0xffffffffu, sum0, 2);
        sum1 += __shfl_xor_sync(0xffffffffu, sum1, 1);
        sum1 += __shfl_xor_sync(0xffffffffu, sum1, 2);
        lr0 = lr0 * corr0 + sum0;
        lr1 = lr1 * corr1 + sum1;

        uint32_t pfh[16], pfl[16];
#pragma unroll
        for (int ks = 0; ks < 4; ks++) {
            pfh[ks * 4 + 0] = pack_hi2(S[2 * ks][0],     S[2 * ks][1]);
            pfh[ks * 4 + 1] = pack_hi2(S[2 * ks][2],     S[2 * ks][3]);
            pfh[ks * 4 + 2] = pack_hi2(S[2 * ks + 1][0], S[2 * ks + 1][1]);
            pfh[ks * 4 + 3] = pack_hi2(S[2 * ks + 1][2], S[2 * ks + 1][3]);
            pfl[ks * 4 + 0] = pack_lo2(S[2 * ks][0],     S[2 * ks][1]);
            pfl[ks * 4 + 1] = pack_lo2(S[2 * ks][2],     S[2 * ks][3]);
            pfl[ks * 4 + 2] = pack_lo2(S[2 * ks + 1][0], S[2 * ks + 1][1]);
            pfl[ks * 4 + 3] = pack_lo2(S[2 * ks + 1][2], S[2 * ks + 1][3]);
        }
#pragma unroll
        for (int ks = 0; ks < 4; ks++) {
            const uint32_t vjo = (bv_j + (uint32_t)(ks * 16)) * APB;
#pragma unroll
            for (int np = 0; np < 4; np++) {
                const uint32_t vro = vjo + (bv_d + (uint32_t)(np * 16)) * 2u;
                uint32_t bvh[4], bvl[4];
                LDSM_X4T(bvh[0], bvh[1], bvh[2], bvh[3], Vh + vro);
                LDSM_X4T(bvl[0], bvl[1], bvl[2], bvl[3], Vl + vro);
                MMA16816(O[2 * np],     &pfh[ks * 4], bvh[0], bvh[1]);
                MMA16816(O[2 * np + 1], &pfh[ks * 4], bvh[2], bvh[3]);
                MMA16816(O[2 * np],     &pfh[ks * 4], bvl[0], bvl[1]);
                MMA16816(O[2 * np + 1], &pfh[ks * 4], bvl[2], bvl[3]);
                MMA16816(O[2 * np],     &pfl[ks * 4], bvh[0], bvh[1]);
                MMA16816(O[2 * np + 1], &pfl[ks * 4], bvh[2], bvh[3]);
            }
        }
    }

    const float inv0 = 1.0f / lr0, inv1 = 1.0f / lr1;
    const size_t row0g = (size_t)(b * S_ + q0 + w * 16 + (l >> 2));
    const size_t row1g = row0g + 8;
#pragma unroll
    for (int n = 0; n < 8; n++) {
        const int d0 = h * HD_ + n * 8 + (l & 3) * 2;
        float v0 = O[n][0] * inv0, v1 = O[n][1] * inv0;
        float v2 = O[n][2] * inv1, v3 = O[n][3] * inv1;
        *(uint32_t*)(outh + row0g * D_ + d0) = pack_hi2(v0, v1);
        *(uint32_t*)(outl + row0g * D_ + d0) = pack_lo2(v0, v1);
        *(uint32_t*)(outh + row1g * D_ + d0) = pack_hi2(v2, v3);
        *(uint32_t*)(outl + row1g * D_ + d0) = pack_lo2(v2, v3);
    }
}

// ---------------------------------------------------------------------------
extern "C" void kernel_launch(void* const* d_in, const int* in_sizes, int n_in,
                              void* d_out, int out_size)
{
    const float* x = nullptr; const float* wqkv = nullptr; const float* wout = nullptr;
    for (int i = 0; i < n_in; i++) {
        if (in_sizes[i] == 8388608)      x    = (const float*)d_in[i];
        else if (in_sizes[i] == 3145728) wqkv = (const float*)d_in[i];
        else if (in_sizes[i] == 1048576) wout = (const float*)d_in[i];
    }
    float* out = (float*)d_out;

    void* p;
    cudaGetSymbolAddress(&p, g_qkvh);     __nv_bfloat16* qkvh = (__nv_bfloat16*)p;
    cudaGetSymbolAddress(&p, g_qkvl);     __nv_bfloat16* qkvl = (__nv_bfloat16*)p;
    cudaGetSymbolAddress(&p, g_x_hi);     __nv_bfloat16* x_hi = (__nv_bfloat16*)p;
    cudaGetSymbolAddress(&p, g_x_lo);     __nv_bfloat16* x_lo = (__nv_bfloat16*)p;
    cudaGetSymbolAddress(&p, g_attn_hi);  __nv_bfloat16* a_hi = (__nv_bfloat16*)p;
    cudaGetSymbolAddress(&p, g_attn_lo);  __nv_bfloat16* a_lo = (__nv_bfloat16*)p;
    cudaGetSymbolAddress(&p, g_wqkvT_hi); __nv_bfloat16* wq_hi = (__nv_bfloat16*)p;
    cudaGetSymbolAddress(&p, g_wqkvT_lo); __nv_bfloat16* wq_lo = (__nv_bfloat16*)p;
    cudaGetSymbolAddress(&p, g_woutT_hi); __nv_bfloat16* wo_hi = (__nv_bfloat16*)p;
    cudaGetSymbolAddress(&p, g_woutT_lo); __nv_bfloat16* wo_lo = (__nv_bfloat16*)p;

    cudaFuncSetAttribute(gemm_mma_kernel, cudaFuncAttributeMaxDynamicSharedMemorySize,
                         GEMM_SMEM_BYTES);
    cudaFuncSetAttribute(attn_mma_kernel, cudaFuncAttributeMaxDynamicSharedMemorySize,
                         ATTN_SMEM_BYTES);

    // Weight split+transpose
    tsplit_kernel<<<dim3(3 * D_ / 32, D_ / 32), dim3(32, 8)>>>(wqkv, wq_hi, wq_lo, D_, 3 * D_);
    tsplit_kernel<<<dim3(D_ / 32, D_ / 32), dim3(32, 8)>>>(wout, wo_hi, wo_lo, D_, D_);
    // x split
    split_kernel<<<(M_ * D_ / 4 + 255) / 256, 256>>>(x, x_hi, x_lo, M_ * D_ / 4);

    // 1) qkv(hi/lo) = x @ W_qkv  (Q block pre-scaled by 0.125*log2e)
    gemm_mma_kernel<<<dim3(3 * D_ / 128, M_ / 128), 256, GEMM_SMEM_BYTES>>>(
        x_hi, x_lo, wq_hi, wq_lo, nullptr, qkvh, qkvl, 3 * D_, D_, 1);

    // 2) attention (big-first qt order)
    attn_mma_kernel<<<dim3(S_ / 128, H_, B_), 256, ATTN_SMEM_BYTES>>>(qkvh, qkvl, a_hi, a_lo);

    // 3) out = attn @ W_out  (fp32 out)
    gemm_mma_kernel<<<dim3(D_ / 128, M_ / 128), 256, GEMM_SMEM_BYTES>>>(
        a_hi, a_lo, wo_hi, wo_lo, out, nullptr, nullptr, D_, D_, 0);
}

// round 17
// speedup vs baseline: 1.2092x; 1.2092x over previous
#include <cuda_runtime.h>
#include <cuda_bf16.h>
#include <cuda_fp16.h>
#include <math.h>
#include <cstdint>

// Problem constants
#define B_  4
#define S_  2048
#define D_  1024
#define H_  16
#define HD_ 64
#define M_  (B_ * S_)        // 8192 rows

// Scratch buffers
__device__ __nv_bfloat16 g_qkvh[(size_t)M_ * 3 * D_];   // [8192][3072]
__device__ __nv_bfloat16 g_qkvl[(size_t)M_ * 3 * D_];
__device__ __half g_x_h[(size_t)M_ * D_];               // x in fp16
__device__ __half g_attn_h[(size_t)M_ * D_];            // attn out in fp16
__device__ __half g_wqkvT_hi[(size_t)3 * D_ * D_];      // [3072][1024] fp16 hi
__device__ __half g_wqkvT_lo[(size_t)3 * D_ * D_];      // fp16 lo
__device__ __half g_woutT_hi[(size_t)D_ * D_];          // [1024][1024]
__device__ __half g_woutT_lo[(size_t)D_ * D_];

// ---------------------------------------------------------------------------
// PTX helpers (baseline PTX only: ldmatrix, mma.sync, cp.async)
// ---------------------------------------------------------------------------
__device__ __forceinline__ uint32_t smem_u32(const void* p) {
    uint32_t a;
    asm("{ .reg .u64 t; cvta.to.shared.u64 t, %1; cvt.u32.u64 %0, t; }" : "=r"(a) : "l"(p));
    return a;
}
__device__ __forceinline__ void cpa16(uint32_t s, const void* g) {
    asm volatile("cp.async.cg.shared.global [%0], [%1], 16;" :: "r"(s), "l"(g));
}
#define CPA_COMMIT() asm volatile("cp.async.commit_group;" ::: "memory")
#define CPA_WAIT(n)  asm volatile("cp.async.wait_group %0;" :: "n"(n) : "memory")

#define LDSM_X4(r0, r1, r2, r3, addr) \
    asm volatile("ldmatrix.sync.aligned.m8n8.x4.shared.b16 {%0,%1,%2,%3}, [%4];" \
                 : "=r"(r0), "=r"(r1), "=r"(r2), "=r"(r3) : "r"(addr))
#define LDSM_X4T(r0, r1, r2, r3, addr) \
    asm volatile("ldmatrix.sync.aligned.m8n8.x4.trans.shared.b16 {%0,%1,%2,%3}, [%4];" \
                 : "=r"(r0), "=r"(r1), "=r"(r2), "=r"(r3) : "r"(addr))

// bf16 mma (attention)
#define MMA16816(d, a, bb0, bb1) \
    asm volatile("mma.sync.aligned.m16n8k16.row.col.f32.bf16.bf16.f32 " \
                 "{%0,%1,%2,%3}, {%4,%5,%6,%7}, {%8,%9}, {%0,%1,%2,%3};" \
                 : "+f"((d)[0]), "+f"((d)[1]), "+f"((d)[2]), "+f"((d)[3]) \
                 : "r"((a)[0]), "r"((a)[1]), "r"((a)[2]), "r"((a)[3]), \
                   "r"(bb0), "r"(bb1))
// fp16 mma (projection GEMMs)
#define MMAH16816(d, a, bb0, bb1) \
    asm volatile("mma.sync.aligned.m16n8k16.row.col.f32.f16.f16.f32 " \
                 "{%0,%1,%2,%3}, {%4,%5,%6,%7}, {%8,%9}, {%0,%1,%2,%3};" \
                 : "+f"((d)[0]), "+f"((d)[1]), "+f"((d)[2]), "+f"((d)[3]) \
                 : "r"((a)[0]), "r"((a)[1]), "r"((a)[2]), "r"((a)[3]), \
                   "r"(bb0), "r"(bb1))

__device__ __forceinline__ uint32_t pack_hi2(float a, float b) {
    return (uint32_t)__bfloat16_as_ushort(__float2bfloat16(a))
         | ((uint32_t)__bfloat16_as_ushort(__float2bfloat16(b)) << 16);
}
__device__ __forceinline__ uint32_t pack_lo2(float a, float b) {
    __nv_bfloat16 ha = __float2bfloat16(a), hb = __float2bfloat16(b);
    __nv_bfloat16 la = __float2bfloat16(a - __bfloat162float(ha));
    __nv_bfloat16 lb = __float2bfloat16(b - __bfloat162float(hb));
    return (uint32_t)__bfloat16_as_ushort(la) | ((uint32_t)__bfloat16_as_ushort(lb) << 16);
}
__device__ __forceinline__ uint32_t pack_h2(float a, float b) {
    return (uint32_t)__half_as_ushort(__float2half(a))
         | ((uint32_t)__half_as_ushort(__float2half(b)) << 16);
}

// ---------------------------------------------------------------------------
// fp16 split-2 GEMM:  C = A*Bhi + A*Blo  (A plain fp16; B fp16 hi/lo).
// A [M][K] fp16 row-major, B [N][K] fp16 row-major (weights transposed).
// 3-stage cp.async pipeline, ONE sync/chunk, 64B-pitch + XOR swizzle.
// Tile 128x128, BK=32, 256 threads (8 warps 2x4, warp tile 64x32), 2 CTA/SM.
// Stage: A, Bh, Bl 128x64B each = 24576 B; 3 stages = 73728.
// Output: fp32 (Cf) OR bf16 hi/lo (Ch/Cl) if Cf==nullptr (with Q-block scale).
// ---------------------------------------------------------------------------
#define G_A    0
#define G_BH   8192
#define G_BL   16384
#define G_STG  24576
#define GEMM_SMEM_BYTES (3 * G_STG)       // 73728

__global__ __launch_bounds__(256, 2)
void gemm_mma_kernel(const __half* __restrict__ A,
                     const __half* __restrict__ Bhi, const __half* __restrict__ Blo,
                     float* __restrict__ Cf, __nv_bfloat16* __restrict__ Ch,
                     __nv_bfloat16* __restrict__ Cl, int Ndim, int Kdim, int scaleQ)
{
    extern __shared__ __align__(16) char smem[];
    const uint32_t sb = smem_u32(smem);

    const int t   = threadIdx.x;
    const int l   = t & 31;
    const int wid = t >> 5;
    const int wm  = wid >> 2;             // 0..1
    const int wn  = wid & 3;              // 0..3
    const int row0 = blockIdx.y * 128, col0 = blockIdx.x * 128;

    const int KCH = Kdim >> 5;            // 32

    const int r1 = t >> 2, cc = t & 3;
    const uint32_t scc = (uint32_t)(cc ^ ((r1 >> 1) & 3));
    const uint32_t so1 = (uint32_t)(r1 * 64) + scc * 16;
    const uint32_t so2 = so1 + 64 * 64;

    float acc[4][4][4];
#pragma unroll
    for (int i = 0; i < 4; i++)
#pragma unroll
        for (int j = 0; j < 4; j++)
#pragma unroll
            for (int k = 0; k < 4; k++) acc[i][j][k] = 0.0f;

    const size_t dB = (size_t)(Blo - Bhi);

    auto issue = [&](int c) {
        const int k0 = c << 5;
        const uint32_t base = sb + (uint32_t)(c % 3) * G_STG;
        const __half* a1 = A   + (size_t)(row0 + r1) * Kdim + k0 + cc * 8;
        const __half* a2 = a1 + (size_t)64 * Kdim;
        const __half* b1 = Bhi + (size_t)(col0 + r1) * Kdim + k0 + cc * 8;
        const __half* b2 = b1 + (size_t)64 * Kdim;
        cpa16(base + G_A  + so1, a1);
        cpa16(base + G_A  + so2, a2);
        cpa16(base + G_BH + so1, b1);
        cpa16(base + G_BH + so2, b2);
        cpa16(base + G_BL + so1, b1 + dB);
        cpa16(base + G_BL + so2, b2 + dB);
        CPA_COMMIT();
    };

    issue(0);
    if (KCH > 1) issue(1);

    const uint32_t a_lrow = (uint32_t)(wm * 64 + (l & 15));
    const uint32_t a_cb   = (uint32_t)(l >> 4);
    const uint32_t sa     = (a_lrow >> 1) & 3;
    const uint32_t b_lrow = (uint32_t)(wn * 32 + ((l >> 4) & 1) * 8 + (l & 7));
    const uint32_t b_cb   = (uint32_t)((l >> 3) & 1);
    const uint32_t sbw    = (b_lrow >> 1) & 3;

    for (int c = 0; c < KCH; c++) {
        if (c + 1 < KCH) CPA_WAIT(1); else CPA_WAIT(0);
        __syncthreads();
        if (c + 2 < KCH) issue(c + 2);

        const uint32_t stg = sb + (uint32_t)(c % 3) * G_STG;
        const uint32_t As = stg + G_A;
        const uint32_t Bh = stg + G_BH, Bl = stg + G_BL;
#pragma unroll
        for (int ks = 0; ks < 2; ks++) {
            const uint32_t bsw = ((b_cb + (uint32_t)(ks * 2)) ^ sbw) * 16u;
            uint32_t bfh[2][4], bfl[2][4];
#pragma unroll
            for (int np = 0; np < 2; np++) {
                const uint32_t ro = (b_lrow + (uint32_t)(np * 16)) * 64u + bsw;
                LDSM_X4(bfh[np][0], bfh[np][1], bfh[np][2], bfh[np][3], Bh + ro);
                LDSM_X4(bfl[np][0], bfl[np][1], bfl[np][2], bfl[np][3], Bl + ro);
            }
            const uint32_t asw = ((a_cb + (uint32_t)(ks * 2)) ^ sa) * 16u;
#pragma unroll
            for (int mt = 0; mt < 4; mt++) {
                const uint32_t aro = (a_lrow + (uint32_t)(mt * 16)) * 64u + asw;
                uint32_t af[4];
                LDSM_X4(af[0], af[1], af[2], af[3], As + aro);
#pragma unroll
                for (int nt = 0; nt < 4; nt++) {
                    const uint32_t* bp = &bfh[nt >> 1][(nt & 1) * 2];
                    MMAH16816(acc[mt][nt], af, bp[0], bp[1]);
                }
#pragma unroll
                for (int nt = 0; nt < 4; nt++) {
                    const uint32_t* bp = &bfl[nt >> 1][(nt & 1) * 2];
                    MMAH16816(acc[mt][nt], af, bp[0], bp[1]);
                }
            }
        }
    }

    // Epilogue
    const int erow = row0 + wm * 64 + (l >> 2);
    const int ecol = col0 + wn * 32 + 2 * (l & 3);
    if (Cf) {
#pragma unroll
        for (int mt = 0; mt < 4; mt++)
#pragma unroll
            for (int nt = 0; nt < 4; nt++) {
                float2 v0 = {acc[mt][nt][0], acc[mt][nt][1]};
                float2 v1 = {acc[mt][nt][2], acc[mt][nt][3]};
                *(float2*)(Cf + (size_t)(erow + mt * 16)     * Ndim + ecol + nt * 8) = v0;
                *(float2*)(Cf + (size_t)(erow + mt * 16 + 8) * Ndim + ecol + nt * 8) = v1;
            }
    } else {
        // 0.125 (1/sqrt(64)) * log2(e): S emerges in log2 units -> exp2 softmax
        const float cs = (scaleQ && col0 < 1024) ? 0.18033688011112042f : 1.0f;
#pragma unroll
        for (int mt = 0; mt < 4; mt++)
#pragma unroll
            for (int nt = 0; nt < 4; nt++) {
                float a0 = acc[mt][nt][0] * cs, a1 = acc[mt][nt][1] * cs;
                float a2 = acc[mt][nt][2] * cs, a3 = acc[mt][nt][3] * cs;
                size_t o0 = (size_t)(erow + mt * 16)     * Ndim + ecol + nt * 8;
                size_t o1 = (size_t)(erow + mt * 16 + 8) * Ndim + ecol + nt * 8;
                *(uint32_t*)(Ch + o0) = pack_hi2(a0, a1);
                *(uint32_t*)(Cl + o0) = pack_lo2(a0, a1);
                *(uint32_t*)(Ch + o1) = pack_hi2(a2, a3);
                *(uint32_t*)(Cl + o1) = pack_lo2(a2, a3);
            }
    }
}

// ---------------------------------------------------------------------------
// fp32 -> fp16, elementwise (x input)
// ---------------------------------------------------------------------------
__global__ __launch_bounds__(256) void tohalf_kernel(
    const float* __restrict__ in, __half* __restrict__ out, int n4)
{
    int i = blockIdx.x * blockDim.x + threadIdx.x;
    if (i >= n4) return;
    float4 v = ((const float4*)in)[i];
    uint2 ph = {pack_h2(v.x, v.y), pack_h2(v.z, v.w)};
    ((uint2*)out)[i] = ph;
}

// ---------------------------------------------------------------------------
// fp32 [R][C] -> transposed fp16 hi/lo [C][R]  (weights)
// ---------------------------------------------------------------------------
__global__ void tsplit_kernel(const float* __restrict__ in,
                              __half* __restrict__ hiT,
                              __half* __restrict__ loT, int R, int Cc)
{
    __shared__ float sm2[32][33];
    int c0 = blockIdx.x * 32, r0 = blockIdx.y * 32;
    int tx = threadIdx.x, ty = threadIdx.y;
#pragma unroll
    for (int i = ty; i < 32; i += 8)
        sm2[i][tx] = in[(size_t)(r0 + i) * Cc + c0 + tx];
    __syncthreads();
#pragma unroll
    for (int i = ty; i < 32; i += 8) {
        float v = sm2[tx][i];
        __half h = __float2half(v);
        __half lo = __float2half(v - __half2float(h));
        size_t o = (size_t)(c0 + i) * R + r0 + tx;
        hiT[o] = h; loT[o] = lo;
    }
}

// ---------------------------------------------------------------------------
// Causal flash attention (bf16 split-3 internals unchanged), 2-stage KV
// pipeline, one sync/k-tile, masked-warp skip, exp2 softmax.
// Output: single fp16 array (feeds fp16-split-2 GEMM2).
// ---------------------------------------------------------------------------
#define APB 144
#define AQ_OFF  0
#define AQL_OFF (128 * APB)
#define ASTG0   (2 * 128 * APB)
#define ASTGSZ  (4 * 64 * APB)
#define ATTN_SMEM_BYTES (ASTG0 + 2 * ASTGSZ)   // 110592

__global__ __launch_bounds__(256, 2)
void attn_mma_kernel(const __nv_bfloat16* __restrict__ qkvh,
                     const __nv_bfloat16* __restrict__ qkvl,
                     __half* __restrict__ outf)
{
    extern __shared__ __align__(16) char smem[];
    const uint32_t sb = smem_u32(smem);

    const int t = threadIdx.x, l = t & 31, w = t >> 5;
    const int qt = (int)(gridDim.x - 1 - blockIdx.x);   // big-first scheduling
    const int h = blockIdx.y, b = blockIdx.z;
    const int q0 = qt * 128;

    {
#pragma unroll
        for (int i = 0; i < 4; i++) {
            int q = t + i * 256;
            int r = q >> 3, ch = q & 7;
            size_t g = (size_t)(b * S_ + q0 + r) * 3072 + h * HD_ + ch * 8;
            uint32_t s = (uint32_t)(r * APB + ch * 16);
            cpa16(sb + AQ_OFF + s,  qkvh + g);
            cpa16(sb + AQL_OFF + s, qkvl + g);
        }
        CPA_COMMIT();
    }

    const int r_ld = t >> 3, ch_ld = t & 7;
    const uint32_t s_ld = (uint32_t)(r_ld * APB + ch_ld * 16);
    const uint32_t s_ld2 = s_ld + 32 * APB;

    auto issue_kv = [&](int kt) {
        const int k0 = kt * 64;
        const uint32_t base = sb + ASTG0 + (uint32_t)(kt & 1) * ASTGSZ;
        size_t gk1 = (size_t)(b * S_ + k0 + r_ld) * 3072 + 1024 + h * HD_ + ch_ld * 8;
        size_t gk2 = gk1 + (size_t)32 * 3072;
        cpa16(base + s_ld,          qkvh + gk1);
        cpa16(base + s_ld2,         qkvh + gk2);
        cpa16(base + 9216 + s_ld,   qkvl + gk1);
        cpa16(base + 9216 + s_ld2,  qkvl + gk2);
        cpa16(base + 18432 + s_ld,  qkvh + gk1 + 1024);
        cpa16(base + 18432 + s_ld2, qkvh + gk2 + 1024);
        cpa16(base + 27648 + s_ld,  qkvl + gk1 + 1024);
        cpa16(base + 27648 + s_ld2, qkvl + gk2 + 1024);
        CPA_COMMIT();
    };

    issue_kv(0);

    float m0 = -INFINITY, m1 = -INFINITY, lr0 = 0.0f, lr1 = 0.0f;
    float O[8][4];
#pragma unroll
    for (int n = 0; n < 8; n++)
#pragma unroll
        for (int k = 0; k < 4; k++) O[n][k] = 0.0f;

    const uint32_t a_row = (uint32_t)(w * 16 + (l & 15));
    const uint32_t a_kd  = (uint32_t)((l >> 4) * 8);
    const uint32_t bk_j  = (uint32_t)(((l >> 4) & 1) * 8 + (l & 7));
    const uint32_t bk_d  = (uint32_t)(((l >> 3) & 1) * 8);
    const uint32_t bv_j  = (uint32_t)(((l >> 3) & 1) * 8 + (l & 7));
    const uint32_t bv_d  = (uint32_t)((l >> 4) * 8);

    const int ktiles = 2 * qt + 2;
    for (int kt = 0; kt < ktiles; kt++) {
        const int k0 = kt * 64;
        CPA_WAIT(0);
        __syncthreads();
        if (kt + 1 < ktiles) issue_kv(kt + 1);

        if (k0 > q0 + w * 16 + 15) continue;

        const uint32_t stg = sb + ASTG0 + (uint32_t)(kt & 1) * ASTGSZ;
        const uint32_t Kh = stg, Kl = stg + 9216;
        const uint32_t Vh = stg + 18432, Vl = stg + 27648;

        float S[8][4];
#pragma unroll
        for (int n = 0; n < 8; n++)
#pragma unroll
            for (int k = 0; k < 4; k++) S[n][k] = 0.0f;

#pragma unroll
        for (int ks = 0; ks < 4; ks++) {
            const uint32_t qro = a_row * APB + (a_kd + (uint32_t)(ks * 16)) * 2u;
            uint32_t aqh[4], aql[4];
            LDSM_X4(aqh[0], aqh[1], aqh[2], aqh[3], sb + AQ_OFF + qro);
            LDSM_X4(aql[0], aql[1], aql[2], aql[3], sb + AQL_OFF + qro);
            const uint32_t kdo = (bk_d + (uint32_t)(ks * 16)) * 2u;
#pragma unroll
            for (int jp = 0; jp < 4; jp++) {
                const uint32_t kro = (bk_j + (uint32_t)(jp * 16)) * APB + kdo;
                uint32_t bkh[4], bkl[4];
                LDSM_X4(bkh[0], bkh[1], bkh[2], bkh[3], Kh + kro);
                LDSM_X4(bkl[0], bkl[1], bkl[2], bkl[3], Kl + kro);
                MMA16816(S[2 * jp],     aqh, bkh[0], bkh[1]);
                MMA16816(S[2 * jp + 1], aqh, bkh[2], bkh[3]);
                MMA16816(S[2 * jp],     aqh, bkl[0], bkl[1]);
                MMA16816(S[2 * jp + 1], aqh, bkl[2], bkl[3]);
                MMA16816(S[2 * jp],     aql, bkh[0], bkh[1]);
                MMA16816(S[2 * jp + 1], aql, bkh[2], bkh[3]);
            }
        }

        if (kt >= 2 * qt) {
            const int gi0 = q0 + w * 16 + (l >> 2);
            const int gi1 = gi0 + 8;
#pragma unroll
            for (int n = 0; n < 8; n++) {
                const int gj = k0 + n * 8 + (l & 3) * 2;
                if (gj     > gi0) S[n][0] = -INFINITY;
                if (gj + 1 > gi0) S[n][1] = -INFINITY;
                if (gj     > gi1) S[n][2] = -INFINITY;
                if (gj + 1 > gi1) S[n][3] = -INFINITY;
            }
        }

        float mx0 = -INFINITY, mx1 = -INFINITY;
#pragma unroll
        for (int n = 0; n < 8; n++) {
            mx0 = fmaxf(mx0, fmaxf(S[n][0], S[n][1]));
            mx1 = fmaxf(mx1, fmaxf(S[n][2], S[n][3]));
        }
        mx0 = fmaxf(mx0, __shfl_xor_sync(0xffffffffu, mx0, 1));
        mx0 = fmaxf(mx0, __shfl_xor_sync(0xffffffffu, mx0, 2));
        mx1 = fmaxf(mx1, __shfl_xor_sync(0xffffffffu, mx1, 1));
        mx1 = fmaxf(mx1, __shfl_xor_sync(0xffffffffu, mx1, 2));
        const float mn0 = fmaxf(m0, mx0), mn1 = fmaxf(m1, mx1);
        const float corr0 = exp2f(m0 - mn0), corr1 = exp2f(m1 - mn1);
        m0 = mn0; m1 = mn1;
        float sum0 = 0.0f, sum1 = 0.0f;
#pragma unroll
        for (int n = 0; n < 8; n++) {
            S[n][0] = exp2f(S[n][0] - mn0);
            S[n][1] = exp2f(S[n][1] - mn0);
            S[n][2] = exp2f(S[n][2] - mn1);
            S[n][3] = exp2f(S[n][3] - mn1);
            sum0 += S[n][0] + S[n][1];
            sum1 += S[n][2] + S[n][3];
            O[n][0] *= corr0; O[n][1] *= corr0;
            O[n][2] *= corr1; O[n][3] *= corr1;
        }
        sum0 += __shfl_xor_sync(0xffffffffu, sum0, 1);
        sum0 += __shfl_xor_sync(0xffffffffu, sum0, 2);
        sum1 += __shfl_xor_sync(0xffffffffu, sum1, 1);
        sum1 += __shfl_xor_sync(0xffffffffu, sum1, 2);
        lr0 = lr0 * corr0 + sum0;
        lr1 = lr1 * corr1 + sum1;

        uint32_t pfh[16], pfl[16];
#pragma unroll
        for (int ks = 0; ks < 4; ks++) {
            pfh[ks * 4 + 0] = pack_hi2(S[2 * ks][0],     S[2 * ks][1]);
            pfh[ks * 4 + 1] = pack_hi2(S[2 * ks][2],     S[2 * ks][3]);
            pfh[ks * 4 + 2] = pack_hi2(S[2 * ks + 1][0], S[2 * ks + 1][1]);
            pfh[ks * 4 + 3] = pack_hi2(S[2 * ks + 1][2], S[2 * ks + 1][3]);
            pfl[ks * 4 + 0] = pack_lo2(S[2 * ks][0],     S[2 * ks][1]);
            pfl[ks * 4 + 1] = pack_lo2(S[2 * ks][2],     S[2 * ks][3]);
            pfl[ks * 4 + 2] = pack_lo2(S[2 * ks + 1][0], S[2 * ks + 1][1]);
            pfl[ks * 4 + 3] = pack_lo2(S[2 * ks + 1][2], S[2 * ks + 1][3]);
        }
#pragma unroll
        for (int ks = 0; ks < 4; ks++) {
            const uint32_t vjo = (bv_j + (uint32_t)(ks * 16)) * APB;
#pragma unroll
            for (int np = 0; np < 4; np++) {
                const uint32_t vro = vjo + (bv_d + (uint32_t)(np * 16)) * 2u;
                uint32_t bvh[4], bvl[4];
                LDSM_X4T(bvh[0], bvh[1], bvh[2], bvh[3], Vh + vro);
                LDSM_X4T(bvl[0], bvl[1], bvl[2], bvl[3], Vl + vro);
                MMA16816(O[2 * np],     &pfh[ks * 4], bvh[0], bvh[1]);
                MMA16816(O[2 * np + 1], &pfh[ks * 4], bvh[2], bvh[3]);
                MMA16816(O[2 * np],     &pfh[ks * 4], bvl[0], bvl[1]);
                MMA16816(O[2 * np + 1], &pfh[ks * 4], bvl[2], bvl[3]);
                MMA16816(O[2 * np],     &pfl[ks * 4], bvh[0], bvh[1]);
                MMA16816(O[2 * np + 1], &pfl[ks * 4], bvh[2], bvh[3]);
            }
        }
    }

    // epilogue: normalize, write single fp16 output
    const float inv0 = 1.0f / lr0, inv1 = 1.0f / lr1;
    const size_t row0g = (size_t)(b * S_ + q0 + w * 16 + (l >> 2));
    const size_t row1g = row0g + 8;
#pragma unroll
    for (int n = 0; n < 8; n++) {
        const int d0 = h * HD_ + n * 8 + (l & 3) * 2;
        *(uint32_t*)(outf + row0g * D_ + d0) = pack_h2(O[n][0] * inv0, O[n][1] * inv0);
        *(uint32_t*)(outf + row1g * D_ + d0) = pack_h2(O[n][2] * inv1, O[n][3] * inv1);
    }
}

// ---------------------------------------------------------------------------
extern "C" void kernel_launch(void* const* d_in, const int* in_sizes, int n_in,
                              void* d_out, int out_size)
{
    const float* x = nullptr; const float* wqkv = nullptr; const float* wout = nullptr;
    for (int i = 0; i < n_in; i++) {
        if (in_sizes[i] == 8388608)      x    = (const float*)d_in[i];
        else if (in_sizes[i] == 3145728) wqkv = (const float*)d_in[i];
        else if (in_sizes[i] == 1048576) wout = (const float*)d_in[i];
    }
    float* out = (float*)d_out;

    void* p;
    cudaGetSymbolAddress(&p, g_qkvh);     __nv_bfloat16* qkvh = (__nv_bfloat16*)p;
    cudaGetSymbolAddress(&p, g_qkvl);     __nv_bfloat16* qkvl = (__nv_bfloat16*)p;
    cudaGetSymbolAddress(&p, g_x_h);      __half* x_h   = (__half*)p;
    cudaGetSymbolAddress(&p, g_attn_h);   __half* a_h   = (__half*)p;
    cudaGetSymbolAddress(&p, g_wqkvT_hi); __half* wq_hi = (__half*)p;
    cudaGetSymbolAddress(&p, g_wqkvT_lo); __half* wq_lo = (__half*)p;
    cudaGetSymbolAddress(&p, g_woutT_hi); __half* wo_hi = (__half*)p;
    cudaGetSymbolAddress(&p, g_woutT_lo); __half* wo_lo = (__half*)p;

    cudaFuncSetAttribute(gemm_mma_kernel, cudaFuncAttributeMaxDynamicSharedMemorySize,
                         GEMM_SMEM_BYTES);
    cudaFuncSetAttribute(attn_mma_kernel, cudaFuncAttributeMaxDynamicSharedMemorySize,
                         ATTN_SMEM_BYTES);

    // Weight split+transpose (fp16 hi/lo)
    tsplit_kernel<<<dim3(3 * D_ / 32, D_ / 32), dim3(32, 8)>>>(wqkv, wq_hi, wq_lo, D_, 3 * D_);
    tsplit_kernel<<<dim3(D_ / 32, D_ / 32), dim3(32, 8)>>>(wout, wo_hi, wo_lo, D_, D_);
    // x -> fp16
    tohalf_kernel<<<(M_ * D_ / 4 + 255) / 256, 256>>>(x, x_h, M_ * D_ / 4);

    // 1) qkv(bf16 hi/lo) = x @ W_qkv   (fp16 split-2; Q block pre-scaled)
    gemm_mma_kernel<<<dim3(3 * D_ / 128, M_ / 128), 256, GEMM_SMEM_BYTES>>>(
        x_h, wq_hi, wq_lo, nullptr, qkvh, qkvl, 3 * D_, D_, 1);

    // 2) attention -> fp16 attn
    attn_mma_kernel<<<dim3(S_ / 128, H_, B_), 256, ATTN_SMEM_BYTES>>>(qkvh, qkvl, a_h);

    // 3) out(fp32) = attn @ W_out   (fp16 split-2)
    gemm_mma_kernel<<<dim3(D_ / 128, M_ / 128), 256, GEMM_SMEM_BYTES>>>(
        a_h, wo_hi, wo_lo, out, nullptr, nullptr, D_, D_, 0);
}